// round 16
// baseline (speedup 1.0000x reference)
#include <cuda_runtime.h>

// MatrixMemory (FINAL, unchanged R1 configuration).
// Session result: bandwidth-bound at the compulsory-traffic ceiling.
//   y  = state @ query   (per-batch GEMV,  512MiB read,  zero reuse)
//   dM = d_out ⊗ key     (per-batch outer, 512MiB write, zero reuse)
// Harness draws for this exact source: 156.1 / 157.1 / 156.1 / 157.0 us
// (~7.1 TB/s wall, ~89% of 8TB/s HBM spec). Beats all 10 structural
// alternatives tested (direction-split 157.0-158.0, serial split 166,
// persistent 220, wide-lane 217, barrier-free twin 157.2).
//
// One warp per (b,v) row: 2 front-batched LDG.128(.cs) + dot-reduce,
// 2 STG.128(.cs) outer-product row write; q/k staged in smem per block.

#define B_  2048
#define DK_ 256
#define DV_ 256

__global__ __launch_bounds__(256, 8)
void mm_fused_kernel(const float4* __restrict__ state,   // [B, DV, DK] as float4
                     const float*  __restrict__ query,   // [B, DK]
                     const float*  __restrict__ keyv,    // [B, DK]
                     const float*  __restrict__ dout,    // [B, DV]
                     float*        __restrict__ y,       // [B, DV]
                     float4*       __restrict__ dM)      // [B, DV, DK] as float4
{
    const int b     = blockIdx.x >> 5;          // 32 blocks per batch
    const int vbase = (blockIdx.x & 31) << 3;   // 8 v-rows per block

    __shared__ float4 sq[64];   // query[b] as 64 float4
    __shared__ float4 sk[64];   // key[b]   as 64 float4

    const int tid = threadIdx.x;
    if (tid < 64) {
        sq[tid] = reinterpret_cast<const float4*>(query + (long)b * DK_)[tid];
    } else if (tid < 128) {
        sk[tid - 64] = reinterpret_cast<const float4*>(keyv + (long)b * DK_)[tid - 64];
    }
    __syncthreads();

    const int w    = tid >> 5;
    const int lane = tid & 31;
    const int v    = vbase + w;
    const long row = (long)b * DV_ + v;          // global row index (B*DV rows)

    // ---- read state row (1KB) with streaming hint, dot with q ----
    const float4* srow = state + row * (DK_ / 4);
    float4 a0 = __ldcs(srow + lane);             // k = lane*4 .. lane*4+3
    float4 a1 = __ldcs(srow + 32 + lane);        // k = 128 + lane*4 ..

    float4 q0 = sq[lane];
    float4 q1 = sq[lane + 32];

    float s = a0.x * q0.x + a0.y * q0.y + a0.z * q0.z + a0.w * q0.w
            + a1.x * q1.x + a1.y * q1.y + a1.z * q1.z + a1.w * q1.w;

    // warp reduce
    #pragma unroll
    for (int off = 16; off > 0; off >>= 1)
        s += __shfl_xor_sync(0xFFFFFFFFu, s, off);

    // ---- outer-product row write (1KB) with streaming hint ----
    const float dov = __ldg(dout + row);         // scalar, broadcast within warp

    float4 k0 = sk[lane];
    float4 k1 = sk[lane + 32];
    float4 o0 = make_float4(dov * k0.x, dov * k0.y, dov * k0.z, dov * k0.w);
    float4 o1 = make_float4(dov * k1.x, dov * k1.y, dov * k1.z, dov * k1.w);

    float4* drow = dM + row * (DK_ / 4);
    __stcs(drow + lane,      o0);
    __stcs(drow + lane + 32, o1);

    if (lane == 0) y[row] = s;
}

extern "C" void kernel_launch(void* const* d_in, const int* in_sizes, int n_in,
                              void* d_out, int out_size)
{
    const float4* state = (const float4*)d_in[0];
    const float*  query = (const float*) d_in[1];
    const float*  keyv  = (const float*) d_in[2];
    const float*  dov   = (const float*) d_in[3];

    float* out = (float*)d_out;
    float*  y  = out;                              // [B, DV]
    float4* dM = (float4*)(out + (long)B_ * DV_);  // [B, DV, DK]

    dim3 grid(B_ * 32);   // 32 blocks per batch, 8 warps each -> 8 rows/block
    dim3 block(256);
    mm_fused_kernel<<<grid, block>>>(state, query, keyv, dov, y, dM);
}

// round 17
// speedup vs baseline: 1.0107x; 1.0107x over previous
#include <cuda_runtime.h>

// MatrixMemory (R17): R1 per-warp shape at finer CTA granularity.
//   y = state @ query (per-batch GEMV), dM = d_out ⊗ key (per-batch outer)
// 131072 CTAs x 128 threads (4 warps, 1 row/warp) — continuing the
// monotone harness-regime trend: 16K CTAs 158.0us, 24K 157.6, 65K 156.8.
// Per-warp memory pattern identical to R1: 2 LDG.128(.cs) + 2 STG.128(.cs),
// q/k staged in smem (1KB each, shared by the block's 4 rows).

#define B_  2048
#define DK_ 256
#define DV_ 256

__global__ __launch_bounds__(128, 8)
void mm_fused17_kernel(const float4* __restrict__ state,   // [B, DV, DK] as float4
                       const float*  __restrict__ query,   // [B, DK]
                       const float*  __restrict__ keyv,    // [B, DK]
                       const float*  __restrict__ dout,    // [B, DV]
                       float*        __restrict__ y,       // [B, DV]
                       float4*       __restrict__ dM)      // [B, DV, DK] as float4
{
    const int b     = blockIdx.x >> 6;          // 64 blocks per batch
    const int vbase = (blockIdx.x & 63) << 2;   // 4 v-rows per block

    __shared__ float4 sq[64];   // query[b] as 64 float4
    __shared__ float4 sk[64];   // key[b]   as 64 float4

    const int tid = threadIdx.x;
    if (tid < 64) {
        sq[tid] = reinterpret_cast<const float4*>(query + (long)b * DK_)[tid];
    } else {
        sk[tid - 64] = reinterpret_cast<const float4*>(keyv + (long)b * DK_)[tid - 64];
    }
    __syncthreads();

    const int w    = tid >> 5;
    const int lane = tid & 31;
    const int v    = vbase + w;
    const long row = (long)b * DV_ + v;          // global row index (B*DV rows)

    // ---- read state row (1KB) with streaming hint, dot with q ----
    const float4* srow = state + row * (DK_ / 4);
    float4 a0 = __ldcs(srow + lane);             // k = lane*4 .. lane*4+3
    float4 a1 = __ldcs(srow + 32 + lane);        // k = 128 + lane*4 ..

    float4 q0 = sq[lane];
    float4 q1 = sq[lane + 32];

    float s = a0.x * q0.x + a0.y * q0.y + a0.z * q0.z + a0.w * q0.w
            + a1.x * q1.x + a1.y * q1.y + a1.z * q1.z + a1.w * q1.w;

    // warp reduce
    #pragma unroll
    for (int off = 16; off > 0; off >>= 1)
        s += __shfl_xor_sync(0xFFFFFFFFu, s, off);

    // ---- outer-product row write (1KB) with streaming hint ----
    const float dov = __ldg(dout + row);         // scalar, broadcast within warp

    float4 k0 = sk[lane];
    float4 k1 = sk[lane + 32];
    float4 o0 = make_float4(dov * k0.x, dov * k0.y, dov * k0.z, dov * k0.w);
    float4 o1 = make_float4(dov * k1.x, dov * k1.y, dov * k1.z, dov * k1.w);

    float4* drow = dM + row * (DK_ / 4);
    __stcs(drow + lane,      o0);
    __stcs(drow + lane + 32, o1);

    if (lane == 0) y[row] = s;
}

extern "C" void kernel_launch(void* const* d_in, const int* in_sizes, int n_in,
                              void* d_out, int out_size)
{
    const float4* state = (const float4*)d_in[0];
    const float*  query = (const float*) d_in[1];
    const float*  keyv  = (const float*) d_in[2];
    const float*  dov   = (const float*) d_in[3];

    float* out = (float*)d_out;
    float*  y  = out;                              // [B, DV]
    float4* dM = (float4*)(out + (long)B_ * DV_);  // [B, DV, DK]

    dim3 grid(B_ * 64);   // 64 blocks per batch, 4 warps each, 1 row/warp
    dim3 block(128);
    mm_fused17_kernel<<<grid, block>>>(state, query, keyv, dov, y, dM);
}